// round 6
// baseline (speedup 1.0000x reference)
#include <cuda_runtime.h>

// Problem constants.
static constexpr int B_    = 4096;
static constexpr int NPRE  = 16384;
static constexpr int NPOST = 16384;
static constexpr int R_    = 32;
static constexpr int SPLITK = 16;
static constexpr int KRANGE = NPRE / SPLITK;   // 1024
static constexpr int CHUNK  = 32;
static constexpr int NCHUNK = KRANGE / CHUNK;  // 32

// Scratch (__device__ globals; no allocations allowed).
__device__ float g_Zpart[SPLITK * B_ * R_];   // 8 MB  [split][b][r]
__device__ float g_Vhi[NPRE * R_];            // 2 MB  V hi, native [k][n]
__device__ float g_Vlo[NPRE * R_];            // 2 MB
__device__ float g_Uthi[R_ * NPOST];          // 2 MB  U^T hi, [r][n]
__device__ float g_Utlo[R_ * NPOST];          // 2 MB
__device__ float g_Zhi[B_ * R_];              // 512 KB Z hi, [b][r]
__device__ float g_Zlo[B_ * R_];              // 512 KB

// ---------------------------------------------------------------------------
// tf32 helpers + mma.sync (baseline PTX, valid on plain sm_100).
// ---------------------------------------------------------------------------
__device__ __forceinline__ float tf32_rd(float x) {
    unsigned u;
    asm("cvt.rna.tf32.f32 %0, %1;" : "=r"(u) : "f"(x));
    return __uint_as_float(u);
}
__device__ __forceinline__ void split_tf32(float x, float& hi, float& lo) {
    hi = tf32_rd(x);
    lo = tf32_rd(x - hi);
}
// D += A(16x8) * B(8x8), tf32 inputs, f32 accumulate.
__device__ __forceinline__ void mma8(float* d, const float* a, const float* b) {
    asm volatile(
        "mma.sync.aligned.m16n8k8.row.col.f32.tf32.tf32.f32 "
        "{%0,%1,%2,%3}, {%4,%5,%6,%7}, {%8,%9}, {%0,%1,%2,%3};"
        : "+f"(d[0]), "+f"(d[1]), "+f"(d[2]), "+f"(d[3])
        : "r"(__float_as_uint(a[0])), "r"(__float_as_uint(a[1])),
          "r"(__float_as_uint(a[2])), "r"(__float_as_uint(a[3])),
          "r"(__float_as_uint(b[0])), "r"(__float_as_uint(b[1])));
}

// ---------------------------------------------------------------------------
// Pre-passes.
// ---------------------------------------------------------------------------
__global__ void splitV(const float* __restrict__ V) {
    int g = blockIdx.x * blockDim.x + threadIdx.x;   // over NPRE*R_, [k][n]
    float hi, lo;
    split_tf32(V[g], hi, lo);
    g_Vhi[g] = hi;
    g_Vlo[g] = lo;
}
__global__ void transU(const float* __restrict__ U) {
    int g = blockIdx.x * blockDim.x + threadIdx.x;   // g = r*NPOST + n
    int r = g >> 14;
    int n = g & (NPOST - 1);
    float hi, lo;
    split_tf32(U[(size_t)n * R_ + r], hi, lo);
    g_Uthi[g] = hi;
    g_Utlo[g] = lo;
}
__global__ void reduceZ() {
    int g = blockIdx.x * blockDim.x + threadIdx.x;   // g = b*32 + r
    float s = 0.f;
#pragma unroll
    for (int sp = 0; sp < SPLITK; sp++)
        s += g_Zpart[(size_t)sp * B_ * R_ + g];
    float hi, lo;
    split_tf32(s, hi, lo);
    g_Zhi[g] = hi;
    g_Zlo[g] = lo;
}

// ---------------------------------------------------------------------------
// GEMM1: Zpart[split] = S[:, range] @ V[range, :]  (M=128/CTA, N=32, 3-term)
// A smem [m][36] (bank = 4*row+col, conflict-free frag loads);
// B smem [k][40] (bank = 8*k+n). Register prefetch across chunks.
// ---------------------------------------------------------------------------
__global__ __launch_bounds__(128) void gemmA(const float* __restrict__ S) {
    __shared__ float sAhi[128 * 36];
    __shared__ float sAlo[128 * 36];
    __shared__ float sBhi[32 * 40];
    __shared__ float sBlo[32 * 40];

    const int tid = threadIdx.x, wid = tid >> 5, lane = tid & 31;
    const int gq = lane >> 2, tg = lane & 3;         // fragment coords
    const int m0 = blockIdx.x * 128;
    const int k0 = blockIdx.y * KRANGE;

    float acc[2][4][4];
#pragma unroll
    for (int mt = 0; mt < 2; mt++)
#pragma unroll
        for (int nt = 0; nt < 4; nt++)
#pragma unroll
            for (int q = 0; q < 4; q++) acc[mt][nt][q] = 0.f;

    float4 pS[8], pBh[2], pBl[2];
    // Prefetch chunk 0.
#pragma unroll
    for (int i = 0; i < 8; i++) {
        int idx = tid + i * 128, row = idx >> 3, kq = idx & 7;
        pS[i] = *reinterpret_cast<const float4*>(
            &S[(size_t)(m0 + row) * NPRE + k0 + kq * 4]);
    }
#pragma unroll
    for (int i = 0; i < 2; i++) {
        int idx = tid + i * 128, k = idx >> 3, nq = idx & 7;
        pBh[i] = *reinterpret_cast<const float4*>(&g_Vhi[(size_t)(k0 + k) * R_ + nq * 4]);
        pBl[i] = *reinterpret_cast<const float4*>(&g_Vlo[(size_t)(k0 + k) * R_ + nq * 4]);
    }

    for (int c = 0; c < NCHUNK; c++) {
        // Commit prefetched chunk to smem (split S into hi/lo here).
#pragma unroll
        for (int i = 0; i < 8; i++) {
            int idx = tid + i * 128, row = idx >> 3, kq = idx & 7;
            float4 v = pS[i], h, l;
            split_tf32(v.x, h.x, l.x);
            split_tf32(v.y, h.y, l.y);
            split_tf32(v.z, h.z, l.z);
            split_tf32(v.w, h.w, l.w);
            *reinterpret_cast<float4*>(&sAhi[row * 36 + kq * 4]) = h;
            *reinterpret_cast<float4*>(&sAlo[row * 36 + kq * 4]) = l;
        }
#pragma unroll
        for (int i = 0; i < 2; i++) {
            int idx = tid + i * 128, k = idx >> 3, nq = idx & 7;
            *reinterpret_cast<float4*>(&sBhi[k * 40 + nq * 4]) = pBh[i];
            *reinterpret_cast<float4*>(&sBlo[k * 40 + nq * 4]) = pBl[i];
        }
        __syncthreads();

        // Prefetch next chunk (overlaps fragment loads + MMA below).
        if (c + 1 < NCHUNK) {
            const int kn = k0 + (c + 1) * CHUNK;
#pragma unroll
            for (int i = 0; i < 8; i++) {
                int idx = tid + i * 128, row = idx >> 3, kq = idx & 7;
                pS[i] = *reinterpret_cast<const float4*>(
                    &S[(size_t)(m0 + row) * NPRE + kn + kq * 4]);
            }
#pragma unroll
            for (int i = 0; i < 2; i++) {
                int idx = tid + i * 128, k = idx >> 3, nq = idx & 7;
                pBh[i] = *reinterpret_cast<const float4*>(&g_Vhi[(size_t)(kn + k) * R_ + nq * 4]);
                pBl[i] = *reinterpret_cast<const float4*>(&g_Vlo[(size_t)(kn + k) * R_ + nq * 4]);
            }
        }

#pragma unroll
        for (int ks = 0; ks < 4; ks++) {
            const int kc = ks * 8;
            float bh[4][2], bl[4][2];
#pragma unroll
            for (int nt = 0; nt < 4; nt++) {
                bh[nt][0] = sBhi[(kc + tg) * 40 + nt * 8 + gq];
                bh[nt][1] = sBhi[(kc + tg + 4) * 40 + nt * 8 + gq];
                bl[nt][0] = sBlo[(kc + tg) * 40 + nt * 8 + gq];
                bl[nt][1] = sBlo[(kc + tg + 4) * 40 + nt * 8 + gq];
            }
#pragma unroll
            for (int mt = 0; mt < 2; mt++) {
                const int r0 = wid * 32 + mt * 16 + gq;
                float ah[4], al[4];
                ah[0] = sAhi[r0 * 36 + kc + tg];
                ah[1] = sAhi[(r0 + 8) * 36 + kc + tg];
                ah[2] = sAhi[r0 * 36 + kc + tg + 4];
                ah[3] = sAhi[(r0 + 8) * 36 + kc + tg + 4];
                al[0] = sAlo[r0 * 36 + kc + tg];
                al[1] = sAlo[(r0 + 8) * 36 + kc + tg];
                al[2] = sAlo[r0 * 36 + kc + tg + 4];
                al[3] = sAlo[(r0 + 8) * 36 + kc + tg + 4];
#pragma unroll
                for (int nt = 0; nt < 4; nt++) {
                    mma8(acc[mt][nt], ah, bh[nt]);
                    mma8(acc[mt][nt], ah, bl[nt]);
                    mma8(acc[mt][nt], al, bh[nt]);
                }
            }
        }
        __syncthreads();
    }

    // Epilogue: fragment-direct stores (tiny: 1M float2 total across grid).
    float* out = &g_Zpart[(size_t)blockIdx.y * B_ * R_];
#pragma unroll
    for (int mt = 0; mt < 2; mt++) {
        const int row = m0 + wid * 32 + mt * 16 + gq;
#pragma unroll
        for (int nt = 0; nt < 4; nt++) {
            const int col = nt * 8 + tg * 2;
            *reinterpret_cast<float2*>(&out[(size_t)row * R_ + col]) =
                make_float2(acc[mt][nt][0], acc[mt][nt][1]);
            *reinterpret_cast<float2*>(&out[(size_t)(row + 8) * R_ + col]) =
                make_float2(acc[mt][nt][2], acc[mt][nt][3]);
        }
    }
}

// ---------------------------------------------------------------------------
// GEMM2: Y = Z @ U^T. Tile 128b x 128n, 256 threads (8 warps: 2 x 4),
// K=32 one shot, 3-term. Epilogue staged through smem for STG.128.
// ---------------------------------------------------------------------------
static constexpr int SZ_OFF  = 0;                 // sZhi 128*36
static constexpr int SZL_OFF = 128 * 36;          // sZlo
static constexpr int SU_OFF  = 2 * 128 * 36;      // sUhi 32*136
static constexpr int SUL_OFF = 2 * 128 * 36 + 32 * 136;
static constexpr int GEMMB_FLOATS = 2 * 128 * 36 + 2 * 32 * 136;  // 17920
static constexpr int GEMMB_SMEM = GEMMB_FLOATS * 4;               // 71680 B

__global__ __launch_bounds__(256) void gemmB(float* __restrict__ Y) {
    extern __shared__ float dsm[];
    float* sZhi = dsm + SZ_OFF;
    float* sZlo = dsm + SZL_OFF;
    float* sUhi = dsm + SU_OFF;
    float* sUlo = dsm + SUL_OFF;

    const int tid = threadIdx.x, wid = tid >> 5, lane = tid & 31;
    const int gq = lane >> 2, tg = lane & 3;
    const int wm = wid >> 2, wn = wid & 3;        // warp grid 2 x 4
    const int n0 = blockIdx.x * 128;
    const int b0 = blockIdx.y * 128;

    // Stage Z tile [128][32] -> [m][36] hi/lo.
#pragma unroll
    for (int i = 0; i < 4; i++) {
        int idx = tid + i * 256, row = idx >> 3, kq = idx & 7;
        *reinterpret_cast<float4*>(&sZhi[row * 36 + kq * 4]) =
            *reinterpret_cast<const float4*>(&g_Zhi[(size_t)(b0 + row) * R_ + kq * 4]);
        *reinterpret_cast<float4*>(&sZlo[row * 36 + kq * 4]) =
            *reinterpret_cast<const float4*>(&g_Zlo[(size_t)(b0 + row) * R_ + kq * 4]);
    }
    // Stage U^T tile [32][128] -> [k][136] hi/lo.
#pragma unroll
    for (int i = 0; i < 4; i++) {
        int idx = tid + i * 256, r = idx >> 5, ng = idx & 31;
        *reinterpret_cast<float4*>(&sUhi[r * 136 + ng * 4]) =
            *reinterpret_cast<const float4*>(&g_Uthi[(size_t)r * NPOST + n0 + ng * 4]);
        *reinterpret_cast<float4*>(&sUlo[r * 136 + ng * 4]) =
            *reinterpret_cast<const float4*>(&g_Utlo[(size_t)r * NPOST + n0 + ng * 4]);
    }
    __syncthreads();

    float acc[4][4][4];
#pragma unroll
    for (int mt = 0; mt < 4; mt++)
#pragma unroll
        for (int nt = 0; nt < 4; nt++)
#pragma unroll
            for (int q = 0; q < 4; q++) acc[mt][nt][q] = 0.f;

#pragma unroll
    for (int ks = 0; ks < 4; ks++) {
        const int kc = ks * 8;
        float bh[4][2], bl[4][2];
#pragma unroll
        for (int nt = 0; nt < 4; nt++) {
            const int nc = wn * 32 + nt * 8 + gq;
            bh[nt][0] = sUhi[(kc + tg) * 136 + nc];
            bh[nt][1] = sUhi[(kc + tg + 4) * 136 + nc];
            bl[nt][0] = sUlo[(kc + tg) * 136 + nc];
            bl[nt][1] = sUlo[(kc + tg + 4) * 136 + nc];
        }
#pragma unroll
        for (int mt = 0; mt < 4; mt++) {
            const int r0 = wm * 64 + mt * 16 + gq;
            float ah[4], al[4];
            ah[0] = sZhi[r0 * 36 + kc + tg];
            ah[1] = sZhi[(r0 + 8) * 36 + kc + tg];
            ah[2] = sZhi[r0 * 36 + kc + tg + 4];
            ah[3] = sZhi[(r0 + 8) * 36 + kc + tg + 4];
            al[0] = sZlo[r0 * 36 + kc + tg];
            al[1] = sZlo[(r0 + 8) * 36 + kc + tg];
            al[2] = sZlo[r0 * 36 + kc + tg + 4];
            al[3] = sZlo[(r0 + 8) * 36 + kc + tg + 4];
#pragma unroll
            for (int nt = 0; nt < 4; nt++) {
                mma8(acc[mt][nt], ah, bh[nt]);
                mma8(acc[mt][nt], ah, bl[nt]);
                mma8(acc[mt][nt], al, bh[nt]);
            }
        }
    }
    __syncthreads();   // operand tiles dead; reuse smem for epilogue

    // Epilogue: fragments -> smem [128][132], then coalesced STG.128.
    float* sY = dsm;
#pragma unroll
    for (int mt = 0; mt < 4; mt++) {
        const int row = wm * 64 + mt * 16 + gq;
#pragma unroll
        for (int nt = 0; nt < 4; nt++) {
            const int col = wn * 32 + nt * 8 + tg * 2;
            *reinterpret_cast<float2*>(&sY[row * 132 + col]) =
                make_float2(acc[mt][nt][0], acc[mt][nt][1]);
            *reinterpret_cast<float2*>(&sY[(row + 8) * 132 + col]) =
                make_float2(acc[mt][nt][2], acc[mt][nt][3]);
        }
    }
    __syncthreads();
#pragma unroll
    for (int i = 0; i < 16; i++) {
        int idx = tid + i * 256, row = idx >> 5, cg = idx & 31;
        float4 v = *reinterpret_cast<const float4*>(&sY[row * 132 + cg * 4]);
        *reinterpret_cast<float4*>(&Y[(size_t)(b0 + row) * NPOST + n0 + cg * 4]) = v;
    }
}

// ---------------------------------------------------------------------------
// Entry point. Inputs: spikes, U, V, mask_* (masks unused by the reference).
// ---------------------------------------------------------------------------
extern "C" void kernel_launch(void* const* d_in, const int* in_sizes, int n_in,
                              void* d_out, int out_size) {
    const float* spikes = (const float*)d_in[0];
    const float* U      = (const float*)d_in[1];
    const float* V      = (const float*)d_in[2];
    float* Y            = (float*)d_out;

    static bool attr_set = false;
    if (!attr_set) {
        cudaFuncSetAttribute(gemmB, cudaFuncAttributeMaxDynamicSharedMemorySize,
                             GEMMB_SMEM);
        attr_set = true;
    }

    splitV<<<(NPRE * R_) / 256, 256>>>(V);
    transU<<<(R_ * NPOST) / 256, 256>>>(U);
    gemmA<<<dim3(B_ / 128, SPLITK), 128>>>(spikes);
    reduceZ<<<(B_ * R_) / 256, 256>>>();
    gemmB<<<dim3(NPOST / 128, B_ / 128), 256, GEMMB_SMEM>>>(Y);
}

// round 7
// speedup vs baseline: 1.5279x; 1.5279x over previous
#include <cuda_runtime.h>
#include <cuda_bf16.h>

// Problem constants.
static constexpr int B_    = 4096;
static constexpr int NPRE  = 16384;
static constexpr int NPOST = 16384;
static constexpr int R_    = 32;
static constexpr int SPLITK = 16;
static constexpr int KRANGE = NPRE / SPLITK;   // 1024
static constexpr int CHUNK  = 32;
static constexpr int NCHUNK = KRANGE / CHUNK;  // 32

// Scratch (__device__ globals; no allocations allowed).
__device__ float    g_Zpart[SPLITK * B_ * R_];     // 8 MB  [split][b][r] fp32
__device__ unsigned g_Vphi[(NPRE / 2) * R_];       // 1 MB  V packed bf16x2, [kp][n]
__device__ unsigned g_Vplo[(NPRE / 2) * R_];       // 1 MB
__device__ unsigned g_Utphi[(R_ / 2) * NPOST];     // 1 MB  U^T packed, [rp][n]
__device__ unsigned g_Utplo[(R_ / 2) * NPOST];     // 1 MB
__device__ unsigned g_Zphi[B_ * (R_ / 2)];         // 256 KB Z packed, [b][rp]
__device__ unsigned g_Zplo[B_ * (R_ / 2)];         // 256 KB

// ---------------------------------------------------------------------------
// bf16 helpers + mma.sync m16n8k16 (baseline PTX, valid on plain sm_100).
// ---------------------------------------------------------------------------
__device__ __forceinline__ void split_bf(float x, float& hi, float& lo) {
    __nv_bfloat16 h = __float2bfloat16_rn(x);
    hi = __bfloat162float(h);
    lo = x - hi;
}
__device__ __forceinline__ unsigned pack2(float x0, float x1) {  // x0 -> low half
    __nv_bfloat162 t = __floats2bfloat162_rn(x0, x1);
    return *reinterpret_cast<unsigned*>(&t);
}
// D += A(16x16) * B(16x8), bf16 inputs, f32 accumulate.
__device__ __forceinline__ void mma16(float* d, const unsigned* a, const unsigned* b) {
    asm volatile(
        "mma.sync.aligned.m16n8k16.row.col.f32.bf16.bf16.f32 "
        "{%0,%1,%2,%3}, {%4,%5,%6,%7}, {%8,%9}, {%0,%1,%2,%3};"
        : "+f"(d[0]), "+f"(d[1]), "+f"(d[2]), "+f"(d[3])
        : "r"(a[0]), "r"(a[1]), "r"(a[2]), "r"(a[3]), "r"(b[0]), "r"(b[1]));
}

// ---------------------------------------------------------------------------
// Pre-passes: build packed bf16x2 hi/lo operand tensors.
// ---------------------------------------------------------------------------
__global__ void splitV(const float* __restrict__ V) {
    int g = blockIdx.x * blockDim.x + threadIdx.x;  // over (NPRE/2)*R_
    int kp = g >> 5, n = g & 31;
    float x0 = V[(size_t)(2 * kp) * R_ + n];
    float x1 = V[(size_t)(2 * kp + 1) * R_ + n];
    float h0, l0, h1, l1;
    split_bf(x0, h0, l0);
    split_bf(x1, h1, l1);
    g_Vphi[g] = pack2(h0, h1);
    g_Vplo[g] = pack2(l0, l1);
}
__global__ void transU(const float* __restrict__ U) {
    int g = blockIdx.x * blockDim.x + threadIdx.x;  // over 16*NPOST
    int rp = g >> 14, n = g & (NPOST - 1);
    float2 u = *reinterpret_cast<const float2*>(&U[(size_t)n * R_ + 2 * rp]);
    float h0, l0, h1, l1;
    split_bf(u.x, h0, l0);
    split_bf(u.y, h1, l1);
    g_Utphi[g] = pack2(h0, h1);
    g_Utplo[g] = pack2(l0, l1);
}
__global__ void reduceZ() {
    int g = blockIdx.x * blockDim.x + threadIdx.x;  // over B_*16
    int b = g >> 4, rp = g & 15;
    float2 s = make_float2(0.f, 0.f);
#pragma unroll
    for (int sp = 0; sp < SPLITK; sp++) {
        float2 v = *reinterpret_cast<const float2*>(
            &g_Zpart[(size_t)sp * B_ * R_ + (size_t)b * R_ + 2 * rp]);
        s.x += v.x;
        s.y += v.y;
    }
    float h0, l0, h1, l1;
    split_bf(s.x, h0, l0);
    split_bf(s.y, h1, l1);
    g_Zphi[g] = pack2(h0, h1);
    g_Zplo[g] = pack2(l0, l1);
}

// ---------------------------------------------------------------------------
// GEMM1: Zpart[split] = S[:, range] @ V[range, :]  (M=128/CTA, N=32, 3-term)
// A smem: words [m][20] (banks 20*gq+tg -> all 32); B smem: words [kp][36]
// (banks 4*tg+gq -> all 32). Register prefetch across 32-k chunks.
// ---------------------------------------------------------------------------
__global__ __launch_bounds__(128) void gemmA(const float* __restrict__ S) {
    __shared__ unsigned sAhi[128 * 20];
    __shared__ unsigned sAlo[128 * 20];
    __shared__ unsigned sBhi[16 * 36];
    __shared__ unsigned sBlo[16 * 36];

    const int tid = threadIdx.x, wid = tid >> 5, lane = tid & 31;
    const int gq = lane >> 2, tg = lane & 3;
    const int m0 = blockIdx.x * 128;
    const int k0 = blockIdx.y * KRANGE;

    float acc[2][4][4];
#pragma unroll
    for (int mt = 0; mt < 2; mt++)
#pragma unroll
        for (int nt = 0; nt < 4; nt++)
#pragma unroll
            for (int q = 0; q < 4; q++) acc[mt][nt][q] = 0.f;

    // Prefetch chunk 0.
    float4 pS[8];
    uint4 pBh, pBl;
#pragma unroll
    for (int i = 0; i < 8; i++) {
        int idx = tid + i * 128, row = idx >> 3, kq = idx & 7;
        pS[i] = *reinterpret_cast<const float4*>(
            &S[(size_t)(m0 + row) * NPRE + k0 + kq * 4]);
    }
    {
        int kpb = k0 >> 1;
        size_t src = (size_t)(kpb + (tid >> 3)) * R_ + (tid & 7) * 4;
        pBh = *reinterpret_cast<const uint4*>(&g_Vphi[src]);
        pBl = *reinterpret_cast<const uint4*>(&g_Vplo[src]);
    }

    for (int c = 0; c < NCHUNK; c++) {
        // Commit prefetched chunk (split S -> bf16 hi/lo, pack pairs along k).
#pragma unroll
        for (int i = 0; i < 8; i++) {
            int idx = tid + i * 128, row = idx >> 3, kq = idx & 7;
            float4 v = pS[i];
            float h0, l0, h1, l1, h2, l2, h3, l3;
            split_bf(v.x, h0, l0);
            split_bf(v.y, h1, l1);
            split_bf(v.z, h2, l2);
            split_bf(v.w, h3, l3);
            unsigned off = row * 20 + kq * 2;
            *reinterpret_cast<uint2*>(&sAhi[off]) =
                make_uint2(pack2(h0, h1), pack2(h2, h3));
            *reinterpret_cast<uint2*>(&sAlo[off]) =
                make_uint2(pack2(l0, l1), pack2(l2, l3));
        }
        {
            unsigned off = (tid >> 3) * 36 + (tid & 7) * 4;
            *reinterpret_cast<uint4*>(&sBhi[off]) = pBh;
            *reinterpret_cast<uint4*>(&sBlo[off]) = pBl;
        }
        __syncthreads();

        // Prefetch next chunk (overlaps fragment loads + MMA below).
        if (c + 1 < NCHUNK) {
            const int kn = k0 + (c + 1) * CHUNK;
#pragma unroll
            for (int i = 0; i < 8; i++) {
                int idx = tid + i * 128, row = idx >> 3, kq = idx & 7;
                pS[i] = *reinterpret_cast<const float4*>(
                    &S[(size_t)(m0 + row) * NPRE + kn + kq * 4]);
            }
            int kpb = kn >> 1;
            size_t src = (size_t)(kpb + (tid >> 3)) * R_ + (tid & 7) * 4;
            pBh = *reinterpret_cast<const uint4*>(&g_Vphi[src]);
            pBl = *reinterpret_cast<const uint4*>(&g_Vplo[src]);
        }

#pragma unroll
        for (int ks = 0; ks < 2; ks++) {
            unsigned bh[4][2], bl[4][2];
#pragma unroll
            for (int nt = 0; nt < 4; nt++) {
                bh[nt][0] = sBhi[(ks * 8 + tg) * 36 + nt * 8 + gq];
                bh[nt][1] = sBhi[(ks * 8 + tg + 4) * 36 + nt * 8 + gq];
                bl[nt][0] = sBlo[(ks * 8 + tg) * 36 + nt * 8 + gq];
                bl[nt][1] = sBlo[(ks * 8 + tg + 4) * 36 + nt * 8 + gq];
            }
#pragma unroll
            for (int mt = 0; mt < 2; mt++) {
                const int r0 = wid * 32 + mt * 16 + gq;
                unsigned ah[4], al[4];
                ah[0] = sAhi[r0 * 20 + ks * 8 + tg];
                ah[1] = sAhi[(r0 + 8) * 20 + ks * 8 + tg];
                ah[2] = sAhi[r0 * 20 + ks * 8 + tg + 4];
                ah[3] = sAhi[(r0 + 8) * 20 + ks * 8 + tg + 4];
                al[0] = sAlo[r0 * 20 + ks * 8 + tg];
                al[1] = sAlo[(r0 + 8) * 20 + ks * 8 + tg];
                al[2] = sAlo[r0 * 20 + ks * 8 + tg + 4];
                al[3] = sAlo[(r0 + 8) * 20 + ks * 8 + tg + 4];
#pragma unroll
                for (int nt = 0; nt < 4; nt++) {
                    mma16(acc[mt][nt], ah, bh[nt]);
                    mma16(acc[mt][nt], ah, bl[nt]);
                    mma16(acc[mt][nt], al, bh[nt]);
                }
            }
        }
        __syncthreads();
    }

    // Epilogue: fragment-direct fp32 stores (small tensor).
    float* out = &g_Zpart[(size_t)blockIdx.y * B_ * R_];
#pragma unroll
    for (int mt = 0; mt < 2; mt++) {
        const int row = m0 + wid * 32 + mt * 16 + gq;
#pragma unroll
        for (int nt = 0; nt < 4; nt++) {
            const int col = nt * 8 + tg * 2;
            *reinterpret_cast<float2*>(&out[(size_t)row * R_ + col]) =
                make_float2(acc[mt][nt][0], acc[mt][nt][1]);
            *reinterpret_cast<float2*>(&out[(size_t)(row + 8) * R_ + col]) =
                make_float2(acc[mt][nt][2], acc[mt][nt][3]);
        }
    }
}

// ---------------------------------------------------------------------------
// GEMM2: Y = Z @ U^T. Tile 128b x 128n, 256 threads (warps 2 x 4), K=32
// single shot, 3-term bf16. Direct fragment stores (full 32B sectors).
// ---------------------------------------------------------------------------
__global__ __launch_bounds__(256) void gemmB(float* __restrict__ Y) {
    __shared__ unsigned sZhi[128 * 20];
    __shared__ unsigned sZlo[128 * 20];
    __shared__ unsigned sUhi[16 * 132];
    __shared__ unsigned sUlo[16 * 132];

    const int tid = threadIdx.x, wid = tid >> 5, lane = tid & 31;
    const int gq = lane >> 2, tg = lane & 3;
    const int wm = wid >> 2, wn = wid & 3;
    const int n0 = blockIdx.x * 128;
    const int b0 = blockIdx.y * 128;

    // Stage Z tile: 2048 words per buffer = 512 uint4, 2 per thread.
#pragma unroll
    for (int p = 0; p < 2; p++) {
        int idx = tid + p * 256, row = idx >> 2, c4 = (idx & 3) * 4;
        size_t src = (size_t)(b0 + row) * 16 + c4;
        *reinterpret_cast<uint4*>(&sZhi[row * 20 + c4]) =
            *reinterpret_cast<const uint4*>(&g_Zphi[src]);
        *reinterpret_cast<uint4*>(&sZlo[row * 20 + c4]) =
            *reinterpret_cast<const uint4*>(&g_Zplo[src]);
    }
    // Stage U^T tile: [16 rp][128 n] words.
#pragma unroll
    for (int p = 0; p < 2; p++) {
        int idx = tid + p * 256, rp = idx >> 5, n4 = (idx & 31) * 4;
        size_t src = (size_t)rp * NPOST + n0 + n4;
        *reinterpret_cast<uint4*>(&sUhi[rp * 132 + n4]) =
            *reinterpret_cast<const uint4*>(&g_Utphi[src]);
        *reinterpret_cast<uint4*>(&sUlo[rp * 132 + n4]) =
            *reinterpret_cast<const uint4*>(&g_Utplo[src]);
    }
    __syncthreads();

    float acc[4][4][4];
#pragma unroll
    for (int mt = 0; mt < 4; mt++)
#pragma unroll
        for (int nt = 0; nt < 4; nt++)
#pragma unroll
            for (int q = 0; q < 4; q++) acc[mt][nt][q] = 0.f;

#pragma unroll
    for (int ks = 0; ks < 2; ks++) {
        unsigned bh[4][2], bl[4][2];
#pragma unroll
        for (int nt = 0; nt < 4; nt++) {
            const int nc = wn * 32 + nt * 8 + gq;
            bh[nt][0] = sUhi[(ks * 8 + tg) * 132 + nc];
            bh[nt][1] = sUhi[(ks * 8 + tg + 4) * 132 + nc];
            bl[nt][0] = sUlo[(ks * 8 + tg) * 132 + nc];
            bl[nt][1] = sUlo[(ks * 8 + tg + 4) * 132 + nc];
        }
#pragma unroll
        for (int mt = 0; mt < 4; mt++) {
            const int r0 = wm * 64 + mt * 16 + gq;
            unsigned ah[4], al[4];
            ah[0] = sZhi[r0 * 20 + ks * 8 + tg];
            ah[1] = sZhi[(r0 + 8) * 20 + ks * 8 + tg];
            ah[2] = sZhi[r0 * 20 + ks * 8 + tg + 4];
            ah[3] = sZhi[(r0 + 8) * 20 + ks * 8 + tg + 4];
            al[0] = sZlo[r0 * 20 + ks * 8 + tg];
            al[1] = sZlo[(r0 + 8) * 20 + ks * 8 + tg];
            al[2] = sZlo[r0 * 20 + ks * 8 + tg + 4];
            al[3] = sZlo[(r0 + 8) * 20 + ks * 8 + tg + 4];
#pragma unroll
            for (int nt = 0; nt < 4; nt++) {
                mma16(acc[mt][nt], ah, bh[nt]);
                mma16(acc[mt][nt], ah, bl[nt]);
                mma16(acc[mt][nt], al, bh[nt]);
            }
        }
    }

    // Direct fragment stores: 4 lanes x float2 fill each 32B sector.
#pragma unroll
    for (int mt = 0; mt < 4; mt++) {
        const int row = b0 + wm * 64 + mt * 16 + gq;
#pragma unroll
        for (int nt = 0; nt < 4; nt++) {
            const int col = n0 + wn * 32 + nt * 8 + tg * 2;
            *reinterpret_cast<float2*>(&Y[(size_t)row * NPOST + col]) =
                make_float2(acc[mt][nt][0], acc[mt][nt][1]);
            *reinterpret_cast<float2*>(&Y[(size_t)(row + 8) * NPOST + col]) =
                make_float2(acc[mt][nt][2], acc[mt][nt][3]);
        }
    }
}

// ---------------------------------------------------------------------------
// Entry point. Inputs: spikes, U, V, mask_* (masks unused by the reference).
// ---------------------------------------------------------------------------
extern "C" void kernel_launch(void* const* d_in, const int* in_sizes, int n_in,
                              void* d_out, int out_size) {
    const float* spikes = (const float*)d_in[0];
    const float* U      = (const float*)d_in[1];
    const float* V      = (const float*)d_in[2];
    float* Y            = (float*)d_out;

    splitV<<<((NPRE / 2) * R_) / 256, 256>>>(V);
    transU<<<((R_ / 2) * NPOST) / 256, 256>>>(U);
    gemmA<<<dim3(B_ / 128, SPLITK), 128>>>(spikes);
    reduceZ<<<(B_ * (R_ / 2)) / 256, 256>>>();
    gemmB<<<dim3(NPOST / 128, B_ / 128), 256>>>(Y);
}